// round 1
// baseline (speedup 1.0000x reference)
#include <cuda_runtime.h>
#include <cuda_bf16.h>

// GRU anomaly detector: B=2048, T=256, F=128, H=64, G=3H=192.
// One block = 16 batch rows, full T recurrence, weights resident in SMEM.
// 128 blocks, 256 threads. fp32 throughout.

#define Bn 2048
#define Tn 256
#define Fn 128
#define Hn 64
#define Gn 192
#define ROWS 16
#define NTH 256

// SMEM layout in float4 units:
//  w_ih: 192 rows x 33 f4 (128 floats + 4 pad)  -> 6336 f4
//  w_hh: 192 rows x 17 f4 (64 floats + 4 pad)   -> 3264 f4
//  x   : 2 bufs x 16 rows x 33 f4               -> 1056 f4
//  h   : 2 bufs x 16 rows x 17 f4               ->  544 f4
#define WIH_OFF 0
#define WHH_OFF 6336
#define XB_OFF  9600
#define HB_OFF  10656
#define XBUF_F4 528   // 16*33
#define HBUF_F4 272   // 16*17
#define SMEM_F4 11200
#define SMEM_BYTES (SMEM_F4 * 16)

__device__ __forceinline__ float sigmoidf_(float x) {
    return 1.0f / (1.0f + __expf(-x));
}

__global__ void __launch_bounds__(NTH, 1)
gru_fused_kernel(const float* __restrict__ x,
                 const float* __restrict__ w_ih,
                 const float* __restrict__ w_hh,
                 const float* __restrict__ b_ih,
                 const float* __restrict__ b_hh,
                 const float* __restrict__ fc_w,
                 const float* __restrict__ fc_b,
                 float* __restrict__ out) {
    extern __shared__ float4 sm4[];
    float* smf = (float*)sm4;

    const int tid = threadIdx.x;
    const int u  = tid & 63;        // hidden unit 0..63
    const int rg = tid >> 6;        // row group 0..3 (4 rows each)
    const int r0 = blockIdx.x * ROWS;

    // ---- load weights into SMEM (padded strides) ----
    {
        const float4* g4 = (const float4*)w_ih;   // 192*32 f4
        for (int i = tid; i < Gn * (Fn / 4); i += NTH) {
            int g = i >> 5, k4 = i & 31;
            sm4[WIH_OFF + g * 33 + k4] = g4[i];
        }
        const float4* h4 = (const float4*)w_hh;   // 192*16 f4
        for (int i = tid; i < Gn * (Hn / 4); i += NTH) {
            int g = i >> 4, k4 = i & 15;
            sm4[WHH_OFF + g * 17 + k4] = h4[i];
        }
        // zero both h buffers
        float4 z = make_float4(0.f, 0.f, 0.f, 0.f);
        for (int i = tid; i < 2 * HBUF_F4; i += NTH)
            sm4[HB_OFF + i] = z;
    }

    // bias registers
    const float bir = b_ih[u],        biz = b_ih[64 + u],  bin_ = b_ih[128 + u];
    const float bhr = b_hh[u],        bhz = b_hh[64 + u],  bhn = b_hh[128 + u];

    // ---- preload x tile for t=0 ----
    {
        int i4  = tid * 2;                 // 512 f4 per tile, 2 per thread
        int row = i4 >> 5;                 // 32 f4 per row
        int k4  = i4 & 31;
        const float4* src = (const float4*)(x + (size_t)(r0 + row) * Tn * Fn);
        float4 v0 = src[k4];
        float4 v1 = src[k4 + 1];
        sm4[XB_OFF + row * 33 + k4]     = v0;
        sm4[XB_OFF + row * 33 + k4 + 1] = v1;
    }
    __syncthreads();

    // gate row pointers in SMEM (constant over t)
    const float4* wr = sm4 + WIH_OFF + u * 33;
    const float4* wz = sm4 + WIH_OFF + (64 + u) * 33;
    const float4* wn = sm4 + WIH_OFF + (128 + u) * 33;
    const float4* vr = sm4 + WHH_OFF + u * 17;
    const float4* vz = sm4 + WHH_OFF + (64 + u) * 17;
    const float4* vn = sm4 + WHH_OFF + (128 + u) * 17;

    // prefetch indexing (constant)
    const int pf_i4  = tid * 2;
    const int pf_row = pf_i4 >> 5;
    const int pf_k4  = pf_i4 & 31;
    const float* pf_base = x + (size_t)(r0 + pf_row) * Tn * Fn + pf_k4 * 4;

    for (int t = 0; t < Tn; ++t) {
        // issue next-step x loads early
        float4 p0, p1;
        const bool pf = (t + 1 < Tn);
        if (pf) {
            const float4* src = (const float4*)(pf_base + (size_t)(t + 1) * Fn);
            p0 = src[0];
            p1 = src[1];
        }

        const float4* xb = sm4 + XB_OFF + (t & 1) * XBUF_F4;
        const float4* hb = sm4 + HB_OFF + (t & 1) * HBUF_F4;
        float* hnext = (float*)(sm4 + HB_OFF + ((t + 1) & 1) * HBUF_F4);
        const float* hcur = (const float*)hb;

        float axr[4], axz[4], axn[4];   // gx accumulators per row
        float ahr[4], ahz[4], ahn[4];   // gh accumulators per row
        #pragma unroll
        for (int r = 0; r < 4; ++r) {
            axr[r] = bir; axz[r] = biz; axn[r] = bin_;
            ahr[r] = bhr; ahz[r] = bhz; ahn[r] = bhn;
        }

        const float4* xrow0 = xb + (rg * 4 + 0) * 33;
        const float4* xrow1 = xb + (rg * 4 + 1) * 33;
        const float4* xrow2 = xb + (rg * 4 + 2) * 33;
        const float4* xrow3 = xb + (rg * 4 + 3) * 33;

        // ---- gx: K = 128 (32 f4 quads) ----
        #pragma unroll 4
        for (int kq = 0; kq < 32; ++kq) {
            float4 a = wr[kq], b = wz[kq], c = wn[kq];
            float4 xv;
            xv = xrow0[kq];
            axr[0] += xv.x*a.x + xv.y*a.y + xv.z*a.z + xv.w*a.w;
            axz[0] += xv.x*b.x + xv.y*b.y + xv.z*b.z + xv.w*b.w;
            axn[0] += xv.x*c.x + xv.y*c.y + xv.z*c.z + xv.w*c.w;
            xv = xrow1[kq];
            axr[1] += xv.x*a.x + xv.y*a.y + xv.z*a.z + xv.w*a.w;
            axz[1] += xv.x*b.x + xv.y*b.y + xv.z*b.z + xv.w*b.w;
            axn[1] += xv.x*c.x + xv.y*c.y + xv.z*c.z + xv.w*c.w;
            xv = xrow2[kq];
            axr[2] += xv.x*a.x + xv.y*a.y + xv.z*a.z + xv.w*a.w;
            axz[2] += xv.x*b.x + xv.y*b.y + xv.z*b.z + xv.w*b.w;
            axn[2] += xv.x*c.x + xv.y*c.y + xv.z*c.z + xv.w*c.w;
            xv = xrow3[kq];
            axr[3] += xv.x*a.x + xv.y*a.y + xv.z*a.z + xv.w*a.w;
            axz[3] += xv.x*b.x + xv.y*b.y + xv.z*b.z + xv.w*b.w;
            axn[3] += xv.x*c.x + xv.y*c.y + xv.z*c.z + xv.w*c.w;
        }

        const float4* hrow0 = hb + (rg * 4 + 0) * 17;
        const float4* hrow1 = hb + (rg * 4 + 1) * 17;
        const float4* hrow2 = hb + (rg * 4 + 2) * 17;
        const float4* hrow3 = hb + (rg * 4 + 3) * 17;

        // ---- gh: K = 64 (16 f4 quads) ----
        #pragma unroll 4
        for (int kq = 0; kq < 16; ++kq) {
            float4 a = vr[kq], b = vz[kq], c = vn[kq];
            float4 hv;
            hv = hrow0[kq];
            ahr[0] += hv.x*a.x + hv.y*a.y + hv.z*a.z + hv.w*a.w;
            ahz[0] += hv.x*b.x + hv.y*b.y + hv.z*b.z + hv.w*b.w;
            ahn[0] += hv.x*c.x + hv.y*c.y + hv.z*c.z + hv.w*c.w;
            hv = hrow1[kq];
            ahr[1] += hv.x*a.x + hv.y*a.y + hv.z*a.z + hv.w*a.w;
            ahz[1] += hv.x*b.x + hv.y*b.y + hv.z*b.z + hv.w*b.w;
            ahn[1] += hv.x*c.x + hv.y*c.y + hv.z*c.z + hv.w*c.w;
            hv = hrow2[kq];
            ahr[2] += hv.x*a.x + hv.y*a.y + hv.z*a.z + hv.w*a.w;
            ahz[2] += hv.x*b.x + hv.y*b.y + hv.z*b.z + hv.w*b.w;
            ahn[2] += hv.x*c.x + hv.y*c.y + hv.z*c.z + hv.w*c.w;
            hv = hrow3[kq];
            ahr[3] += hv.x*a.x + hv.y*a.y + hv.z*a.z + hv.w*a.w;
            ahz[3] += hv.x*b.x + hv.y*b.y + hv.z*b.z + hv.w*b.w;
            ahn[3] += hv.x*c.x + hv.y*c.y + hv.z*c.z + hv.w*c.w;
        }

        // ---- gates + h update ----
        float hnew[4];
        #pragma unroll
        for (int r = 0; r < 4; ++r) {
            int row = rg * 4 + r;
            float hold = hcur[row * 68 + u];
            float rr = sigmoidf_(axr[r] + ahr[r]);
            float zz = sigmoidf_(axz[r] + ahz[r]);
            float nn = tanhf(axn[r] + rr * ahn[r]);
            hnew[r] = (1.0f - zz) * nn + zz * hold;
        }

        // store prefetched x into the other buffer
        if (pf) {
            float4* xn = sm4 + XB_OFF + ((t + 1) & 1) * XBUF_F4;
            xn[pf_row * 33 + pf_k4]     = p0;
            xn[pf_row * 33 + pf_k4 + 1] = p1;
        }

        // write h_new into the other buffer
        #pragma unroll
        for (int r = 0; r < 4; ++r) {
            int row = rg * 4 + r;
            hnext[row * 68 + u] = hnew[r];
        }

        __syncthreads();
    }

    // ---- final FC: out[b] = h_last . fc_w + fc_b ----
    // h_last lives in buffer (Tn & 1) == 0
    if (tid < ROWS) {
        const float* hf = (const float*)(sm4 + HB_OFF + (Tn & 1) * HBUF_F4);
        float s = fc_b[0];
        #pragma unroll 8
        for (int j = 0; j < Hn; ++j)
            s += hf[tid * 68 + j] * fc_w[j];
        out[r0 + tid] = s;
    }
}

extern "C" void kernel_launch(void* const* d_in, const int* in_sizes, int n_in,
                              void* d_out, int out_size) {
    const float* x    = (const float*)d_in[0];
    const float* w_ih = (const float*)d_in[1];
    const float* w_hh = (const float*)d_in[2];
    const float* b_ih = (const float*)d_in[3];
    const float* b_hh = (const float*)d_in[4];
    const float* fc_w = (const float*)d_in[5];
    const float* fc_b = (const float*)d_in[6];
    float* out = (float*)d_out;

    cudaFuncSetAttribute(gru_fused_kernel,
                         cudaFuncAttributeMaxDynamicSharedMemorySize, SMEM_BYTES);
    gru_fused_kernel<<<Bn / ROWS, NTH, SMEM_BYTES>>>(
        x, w_ih, w_hh, b_ih, b_hh, fc_w, fc_b, out);
}

// round 2
// speedup vs baseline: 1.1168x; 1.1168x over previous
#include <cuda_runtime.h>
#include <cuda_bf16.h>

// GRU: B=2048, T=256, F=128, H=64, G=192.
// 128 blocks x 128 threads. One block = 16 batch rows.
// Thread (u = tid&63, rg = tid>>6) computes hidden unit u for 8 rows.
// All MACs via packed fma.rn.f32x2 (2 MACs/instr).

#define Bn 2048
#define Tn 256
#define Fn 128
#define Hn 64
#define Gn 192
#define ROWS 16
#define NTH 128

// SMEM layout in 16B units (float4 == ulonglong2):
//  w_ih: 192 x 33 (128 fl + pad)  -> 6336
//  w_hh: 192 x 17 (64 fl + pad)   -> 3264
//  x   : 2 x 16 x 33              -> 1056
//  h   : 2 x 16 x 17              ->  544
#define WIH_OFF 0
#define WHH_OFF 6336
#define XB_OFF  9600
#define HB_OFF  10656
#define XBUF_F4 528
#define HBUF_F4 272
#define SMEM_F4 11200
#define SMEM_BYTES (SMEM_F4 * 16)

typedef unsigned long long u64t;

__device__ __forceinline__ void fma2(u64t& d, u64t a, u64t b) {
    asm("fma.rn.f32x2 %0, %1, %2, %0;" : "+l"(d) : "l"(a), "l"(b));
}
__device__ __forceinline__ float2 up2(u64t v) {
    float2 f;
    asm("mov.b64 {%0, %1}, %2;" : "=f"(f.x), "=f"(f.y) : "l"(v));
    return f;
}
__device__ __forceinline__ float hsum(u64t v) {
    float2 f = up2(v);
    return f.x + f.y;
}
__device__ __forceinline__ float sigmoidf_(float x) {
    return 1.0f / (1.0f + __expf(-x));
}
__device__ __forceinline__ float tanh_ap(float x) {
    float r;
    asm("tanh.approx.f32 %0, %1;" : "=f"(r) : "f"(x));
    return r;
}

__global__ void __launch_bounds__(NTH, 1)
gru_fused_kernel(const float* __restrict__ x,
                 const float* __restrict__ w_ih,
                 const float* __restrict__ w_hh,
                 const float* __restrict__ b_ih,
                 const float* __restrict__ b_hh,
                 const float* __restrict__ fc_w,
                 const float* __restrict__ fc_b,
                 float* __restrict__ out) {
    extern __shared__ float4 sm4[];

    const int tid = threadIdx.x;
    const int u   = tid & 63;       // hidden unit
    const int rg  = tid >> 6;       // 0/1, handles rows rg*8 .. rg*8+7
    const int r0  = blockIdx.x * ROWS;

    // ---- weights -> SMEM (padded strides) ----
    {
        const float4* g4 = (const float4*)w_ih;   // 192*32 f4
        for (int i = tid; i < Gn * (Fn / 4); i += NTH) {
            int g = i >> 5, k4 = i & 31;
            sm4[WIH_OFF + g * 33 + k4] = g4[i];
        }
        const float4* h4 = (const float4*)w_hh;   // 192*16 f4
        for (int i = tid; i < Gn * (Hn / 4); i += NTH) {
            int g = i >> 4, k4 = i & 15;
            sm4[WHH_OFF + g * 17 + k4] = h4[i];
        }
        float4 z = make_float4(0.f, 0.f, 0.f, 0.f);
        for (int i = tid; i < 2 * HBUF_F4; i += NTH)
            sm4[HB_OFF + i] = z;
    }

    // combined biases (x-part + h-part for r,z; separate for n)
    const float brz_r = b_ih[u]        + b_hh[u];
    const float brz_z = b_ih[64 + u]   + b_hh[64 + u];
    const float bn_x  = b_ih[128 + u];
    const float bn_h  = b_hh[128 + u];

    // x prefetch indexing: 512 f4/tile, 4 per thread, unit-stride per LDG
    const int pf_row = tid >> 3;            // 16 rows
    const int pf_k0  = tid & 7;             // +8j, j=0..3
    const float* pf_base = x + (size_t)(r0 + pf_row) * Tn * Fn + pf_k0 * 4;

    // ---- preload x for t=0 ----
    {
        const float4* src = (const float4*)pf_base;
        #pragma unroll
        for (int j = 0; j < 4; ++j)
            sm4[XB_OFF + pf_row * 33 + pf_k0 + 8 * j] = src[8 * j];
    }
    __syncthreads();

    const ulonglong2* wr2 = (const ulonglong2*)(sm4 + WIH_OFF + u * 33);
    const ulonglong2* wz2 = (const ulonglong2*)(sm4 + WIH_OFF + (64 + u) * 33);
    const ulonglong2* wn2 = (const ulonglong2*)(sm4 + WIH_OFF + (128 + u) * 33);
    const ulonglong2* vr2 = (const ulonglong2*)(sm4 + WHH_OFF + u * 17);
    const ulonglong2* vz2 = (const ulonglong2*)(sm4 + WHH_OFF + (64 + u) * 17);
    const ulonglong2* vn2 = (const ulonglong2*)(sm4 + WHH_OFF + (128 + u) * 17);

    for (int t = 0; t < Tn; ++t) {
        // prefetch next x tile into registers
        float4 p[4];
        const bool pf = (t + 1 < Tn);
        if (pf) {
            const float4* src = (const float4*)(pf_base + (size_t)(t + 1) * Fn);
            #pragma unroll
            for (int j = 0; j < 4; ++j) p[j] = src[8 * j];
        }

        const ulonglong2* xb2 = (const ulonglong2*)(sm4 + XB_OFF + (t & 1) * XBUF_F4)
                                + (rg * 8) * 33;
        const ulonglong2* hb2 = (const ulonglong2*)(sm4 + HB_OFF + (t & 1) * HBUF_F4)
                                + (rg * 8) * 17;
        const float* hcur = (const float*)(sm4 + HB_OFF + (t & 1) * HBUF_F4);
        float* hnext      = (float*)(sm4 + HB_OFF + ((t + 1) & 1) * HBUF_F4);

        u64t aR[8], aZ[8], aNx[8], aNh[8];
        #pragma unroll
        for (int r = 0; r < 8; ++r) { aR[r] = 0ull; aZ[r] = 0ull; aNx[r] = 0ull; aNh[r] = 0ull; }

        // ---- gx: K=128 (32 x 16B) ----
        #pragma unroll 4
        for (int kq = 0; kq < 32; ++kq) {
            ulonglong2 a = wr2[kq], b = wz2[kq], c = wn2[kq];
            #pragma unroll
            for (int r = 0; r < 8; ++r) {
                ulonglong2 xv = xb2[r * 33 + kq];
                fma2(aR[r],  xv.x, a.x); fma2(aR[r],  xv.y, a.y);
                fma2(aZ[r],  xv.x, b.x); fma2(aZ[r],  xv.y, b.y);
                fma2(aNx[r], xv.x, c.x); fma2(aNx[r], xv.y, c.y);
            }
        }

        // store prefetched x into the other buffer (regs free after this)
        if (pf) {
            float4* xn = sm4 + XB_OFF + ((t + 1) & 1) * XBUF_F4 + pf_row * 33;
            #pragma unroll
            for (int j = 0; j < 4; ++j) xn[pf_k0 + 8 * j] = p[j];
        }

        // ---- gh: K=64 (16 x 16B) ----
        #pragma unroll 4
        for (int kq = 0; kq < 16; ++kq) {
            ulonglong2 a = vr2[kq], b = vz2[kq], c = vn2[kq];
            #pragma unroll
            for (int r = 0; r < 8; ++r) {
                ulonglong2 hv = hb2[r * 17 + kq];
                fma2(aR[r],  hv.x, a.x); fma2(aR[r],  hv.y, a.y);
                fma2(aZ[r],  hv.x, b.x); fma2(aZ[r],  hv.y, b.y);
                fma2(aNh[r], hv.x, c.x); fma2(aNh[r], hv.y, c.y);
            }
        }

        // ---- gates + h update ----
        #pragma unroll
        for (int r = 0; r < 8; ++r) {
            int row = rg * 8 + r;
            float hold = hcur[row * 68 + u];
            float rr = sigmoidf_(hsum(aR[r]) + brz_r);
            float zz = sigmoidf_(hsum(aZ[r]) + brz_z);
            float nn = tanh_ap(hsum(aNx[r]) + bn_x + rr * (hsum(aNh[r]) + bn_h));
            hnext[row * 68 + u] = (1.0f - zz) * nn + zz * hold;
        }

        __syncthreads();
    }

    // ---- final FC ----
    if (tid < ROWS) {
        const float* hf = (const float*)(sm4 + HB_OFF + (Tn & 1) * HBUF_F4);
        float s = fc_b[0];
        #pragma unroll 8
        for (int j = 0; j < Hn; ++j)
            s += hf[tid * 68 + j] * fc_w[j];
        out[r0 + tid] = s;
    }
}

extern "C" void kernel_launch(void* const* d_in, const int* in_sizes, int n_in,
                              void* d_out, int out_size) {
    const float* x    = (const float*)d_in[0];
    const float* w_ih = (const float*)d_in[1];
    const float* w_hh = (const float*)d_in[2];
    const float* b_ih = (const float*)d_in[3];
    const float* b_hh = (const float*)d_in[4];
    const float* fc_w = (const float*)d_in[5];
    const float* fc_b = (const float*)d_in[6];
    float* out = (float*)d_out;

    cudaFuncSetAttribute(gru_fused_kernel,
                         cudaFuncAttributeMaxDynamicSharedMemorySize, SMEM_BYTES);
    gru_fused_kernel<<<Bn / ROWS, NTH, SMEM_BYTES>>>(
        x, w_ih, w_hh, b_ih, b_hh, fc_w, fc_b, out);
}